// round 2
// baseline (speedup 1.0000x reference)
#include <cuda_runtime.h>
#include <math.h>

// Problem constants (fixed by the dataset)
#define N_ROWS   2048
#define LDIM     128
#define FGV      2.0f

// Tiling
#define RPB      32                                   // rows per block chunk
#define SLOTS    4                                    // (i,k) tuples per thread (same i, 4 consecutive k)
#define THREADS  256
#define IK_BLOCKS (LDIM*LDIM/(THREADS*SLOTS))         // 16
#define NCHUNKS   (N_ROWS/RPB)                        // 64
#define GRID      (IK_BLOCKS*NCHUNKS)                 // 1024

// Scratch accumulators (device globals: no allocation allowed)
__device__ double g_loss;
__device__ float  g_fsum;

__global__ void zero_k() {
    g_loss = 0.0;
    g_fsum = 0.0f;
}

__global__ __launch_bounds__(THREADS) void loss_k(
        const float* __restrict__ y_true,
        const float* __restrict__ y_pred,
        const float* __restrict__ y_diff,
        const float* __restrict__ weights)
{
    __shared__ float ds[RPB * LDIM];
    __shared__ float fs[RPB * LDIM];
    __shared__ float redp[THREADS / 32];
    __shared__ float redf[THREADS / 32];

    const int tid = threadIdx.x;
    const int ikb = blockIdx.x & (IK_BLOCKS - 1);   // which (i,k) tile
    const int nch = blockIdx.x >> 4;                // which row chunk
    const int n0  = nch * RPB;

    // ---- stage d = y_true - y_pred and f = (|y_diff|<=2) into smem ----
    float floc = 0.0f;
    for (int idx = tid; idx < RPB * LDIM; idx += THREADS) {
        const int g = n0 * LDIM + idx;
        const float d = y_true[g] - y_pred[g];
        const float f = (fabsf(y_diff[g]) > FGV) ? 0.0f : 1.0f;
        ds[idx] = d;
        fs[idx] = f;
        floc += f;
    }
    __syncthreads();

    // ---- this thread's 4 tuples: fixed i, k in [k0, k0+3] ----
    const int base = (ikb * THREADS + tid) * SLOTS;
    const int i  = base >> 7;          // base / LDIM
    const int k0 = base & (LDIM - 1);  // base % LDIM
    const int j0 = i + k0;

    float S1[SLOTS], S2[SLOTS];
#pragma unroll
    for (int s = 0; s < SLOTS; s++) { S1[s] = 0.0f; S2[s] = 0.0f; }

    if (j0 < LDIM) {   // at least one slot is a live tuple (~half the threads)
        int jc[SLOTS];
#pragma unroll
        for (int s = 0; s < SLOTS; s++) jc[s] = min(j0 + s, LDIM - 1); // clamp like reference
        const bool isk0 = (k0 == 0);

#pragma unroll 4
        for (int r = 0; r < RPB; r++) {
            const float* dr = ds + r * LDIM;
            const float* fr = fs + r * LDIM;
            const float di = dr[i];
            const float fi = fr[i];
#pragma unroll
            for (int s = 0; s < SLOTS; s++) {
                const float dj = dr[jc[s]];
                const float fj = fr[jc[s]];
                float a  = fabsf(di - dj);
                float yf = fi * fj;
                if (s == 0 && isk0) {   // k==0 special case: |d_i|, filter f_i
                    a  = fabsf(di);
                    yf = fi;
                }
                const float b = yf * a;
                S1[s] += b;          // p = 1 term
                S2[s] += b * a;      // p = 2 term
            }
        }
    }

    // ---- apply weights once (invalid j masked to zero, matching `valid`) ----
    float part = 0.0f;
    {
        const float4 w0 = *(const float4*)(weights + i * LDIM + k0);
        const float4 w1 = *(const float4*)(weights + LDIM * LDIM + i * LDIM + k0);
        const float w0a[4] = { w0.x, w0.y, w0.z, w0.w };
        const float w1a[4] = { w1.x, w1.y, w1.z, w1.w };
#pragma unroll
        for (int s = 0; s < SLOTS; s++) {
            const float m = (j0 + s < LDIM) ? 1.0f : 0.0f;
            part += m * (w0a[s] * S1[s] + w1a[s] * S2[s]);
        }
    }

    // ---- block reduction, then device-wide atomic ----
#pragma unroll
    for (int o = 16; o > 0; o >>= 1) {
        part += __shfl_xor_sync(0xffffffffu, part, o);
        floc += __shfl_xor_sync(0xffffffffu, floc, o);
    }
    const int wid = tid >> 5;
    const int lid = tid & 31;
    if (lid == 0) { redp[wid] = part; redf[wid] = floc; }
    __syncthreads();
    if (tid == 0) {
        float p = 0.0f, ff = 0.0f;
#pragma unroll
        for (int w = 0; w < THREADS / 32; w++) { p += redp[w]; ff += redf[w]; }
        atomicAdd(&g_loss, (double)p);
        if (ikb == 0) atomicAdd(&g_fsum, ff);   // each row counted exactly once
    }
}

__global__ void fin_k(float* out) {
    // loss / l / (n * mean(f))  ==  total_loss / sum(f)
    out[0] = (float)(g_loss / (double)g_fsum);
}

extern "C" void kernel_launch(void* const* d_in, const int* in_sizes, int n_in,
                              void* d_out, int out_size)
{
    const float* y_true  = (const float*)d_in[0];
    const float* y_pred  = (const float*)d_in[1];
    const float* y_diff  = (const float*)d_in[2];
    const float* weights = (const float*)d_in[3];
    float* out = (float*)d_out;

    zero_k<<<1, 1>>>();
    loss_k<<<GRID, THREADS>>>(y_true, y_pred, y_diff, weights);
    fin_k<<<1, 1>>>(out);
}

// round 3
// speedup vs baseline: 2.2474x; 2.2474x over previous
#include <cuda_runtime.h>
#include <math.h>

// Problem constants
#define NR   2048
#define L    128
#define FGV  2.0f

// Tiling
#define RPB      32                  // rows per chunk
#define THREADS  256
#define WPB      8                   // warps per block
#define BPC      10                  // blocks per chunk (80 warps / 8)
#define NCHUNKS  (NR / RPB)          // 64
#define GRID     (BPC * NCHUNKS)     // 640
#define SMPAD    160                 // pad so j-overreads stay in-bounds

// Per-block partials (overwritten every launch -> deterministic)
__device__ float    g_part[GRID];
__device__ float    g_fpart[GRID];
__device__ unsigned g_ctr = 0;       // wraps back to 0 via atomicInc every launch

__global__ __launch_bounds__(THREADS) void loss_k(
        const float* __restrict__ y_true,
        const float* __restrict__ y_pred,
        const float* __restrict__ y_diff,
        const float* __restrict__ wts,
        float* __restrict__ out)
{
    __shared__ float ds[RPB * L + SMPAD];
    __shared__ float fs[RPB * L + SMPAD];
    __shared__ float redp[WPB];
    __shared__ float redf[WPB];
    __shared__ bool  s_last;

    const int tid  = threadIdx.x;
    const int bx   = blockIdx.x;
    const int nch  = bx / BPC;            // row chunk
    const int bic  = bx - nch * BPC;      // block-in-chunk 0..9
    const int n0   = nch * RPB;
    const int lane = tid & 31;

    // ---- diag weights (k==0 column of both p-planes), one block per chunk ----
    float w0d[4], w1d[4];
    const int c4 = tid & 31;              // this thread's float4 column group
    if (bic == 0) {
#pragma unroll
        for (int s = 0; s < 4; s++) {
            const int c = 4 * c4 + s;
            w0d[s] = wts[c * L];
            w1d[s] = wts[L * L + c * L];
        }
    }

    // ---- stage d, f into smem; fold diagonal (k=0) term + f-sum on the fly ----
    float floc  = 0.0f;
    float dpart = 0.0f;
    {
        const float4* yt4 = (const float4*)y_true + (size_t)n0 * (L / 4);
        const float4* yp4 = (const float4*)y_pred + (size_t)n0 * (L / 4);
        const float4* yd4 = (const float4*)y_diff + (size_t)n0 * (L / 4);
#pragma unroll
        for (int it = 0; it < RPB * L / 4 / THREADS; it++) {
            const int idx = tid + it * THREADS;
            const float4 t = yt4[idx];
            const float4 p = yp4[idx];
            const float4 q = yd4[idx];
            float4 d4, f4;
            d4.x = t.x - p.x; d4.y = t.y - p.y; d4.z = t.z - p.z; d4.w = t.w - p.w;
            f4.x = (fabsf(q.x) > FGV) ? 0.0f : 1.0f;
            f4.y = (fabsf(q.y) > FGV) ? 0.0f : 1.0f;
            f4.z = (fabsf(q.z) > FGV) ? 0.0f : 1.0f;
            f4.w = (fabsf(q.w) > FGV) ? 0.0f : 1.0f;
            ((float4*)ds)[idx] = d4;
            ((float4*)fs)[idx] = f4;
            floc += (f4.x + f4.y) + (f4.z + f4.w);
            if (bic == 0) {
                dpart += f4.x * (fabsf(d4.x) * w0d[0] + d4.x * d4.x * w1d[0]);
                dpart += f4.y * (fabsf(d4.y) * w0d[1] + d4.y * d4.y * w1d[1]);
                dpart += f4.z * (fabsf(d4.z) * w0d[2] + d4.z * d4.z * w1d[2]);
                dpart += f4.w * (fabsf(d4.w) * w0d[3] + d4.w * d4.w * w1d[3]);
            }
        }
    }
    if (tid < SMPAD) { ds[RPB * L + tid] = 0.0f; fs[RPB * L + tid] = 0.0f; }
    __syncthreads();

    // ---- warp -> (i-band a, j-quadrant wq) map; all warps do identical work ----
    const int gw = bic * WPB + (tid >> 5);   // 0..79 within chunk
    int a, wq;
    if (gw < 32)      { a = gw >> 2;              wq = gw & 3; }
    else if (gw < 56) { a = 8  + (gw - 32) / 3;   wq = (gw - 32) % 3; }
    else if (gw < 72) { a = 16 + ((gw - 56) >> 1); wq = (gw - 56) & 1; }
    else              { a = 24 + (gw - 72);       wq = 0; }
    const int i0 = 4 * a;                 // 16B-aligned i base
    const int j  = i0 + 32 * wq + lane;   // this lane's shared j (may be >= L: masked)

    // ---- hot loop: conflict-free scalar dj/fj + broadcast vector di/fi ----
    float S1[4] = {0, 0, 0, 0}, S2[4] = {0, 0, 0, 0};
#pragma unroll 4
    for (int r = 0; r < RPB; r++) {
        const float* dr = ds + r * L;
        const float* fr = fs + r * L;
        const float  dj = dr[j];
        const float  fj = fr[j];
        const float4 di4 = *(const float4*)(dr + i0);
        const float4 fi4 = *(const float4*)(fr + i0);
        const float di[4] = { di4.x, di4.y, di4.z, di4.w };
        const float fi[4] = { fi4.x, fi4.y, fi4.z, fi4.w };
#pragma unroll
        for (int s = 0; s < 4; s++) {
            const float aa = fabsf(di[s] - dj);
            const float yf = fi[s] * fj;
            const float b  = yf * aa;
            S1[s] += b;         // p = 1
            S2[s] += b * aa;    // p = 2
        }
    }

    // ---- epilogue: apply weights once, mask invalid slots (coalesced loads) ----
    float part = (bic == 0) ? dpart : 0.0f;
#pragma unroll
    for (int s = 0; s < 4; s++) {
        const int  i     = i0 + s;
        const int  k     = j - i;                 // k >= 1 live; k == 0 handled in staging
        const bool valid = (k >= 1) && (j < L);
        const int  kc    = min(max(k, 1), L - 1);
        const float w0 = wts[i * L + kc];
        const float w1 = wts[L * L + i * L + kc];
        part += (valid ? 1.0f : 0.0f) * (w0 * S1[s] + w1 * S2[s]);
    }

    // ---- block reduction -> per-block partial ----
#pragma unroll
    for (int o = 16; o > 0; o >>= 1) {
        part += __shfl_xor_sync(0xffffffffu, part, o);
        floc += __shfl_xor_sync(0xffffffffu, floc, o);
    }
    const int wid = tid >> 5;
    if (lane == 0) { redp[wid] = part; redf[wid] = floc; }
    __syncthreads();
    if (tid == 0) {
        float p = 0.0f, ff = 0.0f;
#pragma unroll
        for (int w = 0; w < WPB; w++) { p += redp[w]; ff += redf[w]; }
        g_part[bx]  = p;
        g_fpart[bx] = ff;
        __threadfence();
        const unsigned old = atomicInc(&g_ctr, GRID - 1);   // wraps to 0 each launch
        s_last = (old == GRID - 1);
    }
    __syncthreads();

    // ---- last block finalizes ----
    if (s_last) {
        __threadfence();
        double lp = 0.0;
        float  fp = 0.0f;
        for (int idx = tid; idx < GRID; idx += THREADS) {
            lp += (double)g_part[idx];
            fp += g_fpart[idx];
        }
#pragma unroll
        for (int o = 16; o > 0; o >>= 1) {
            lp += __shfl_xor_sync(0xffffffffu, lp, o);
            fp += __shfl_xor_sync(0xffffffffu, fp, o);
        }
        __shared__ double dred[WPB];
        __shared__ float  fred[WPB];
        if (lane == 0) { dred[wid] = lp; fred[wid] = fp; }
        __syncthreads();
        if (tid == 0) {
            double lt = 0.0; float ft = 0.0f;
#pragma unroll
            for (int w = 0; w < WPB; w++) { lt += dred[w]; ft += fred[w]; }
            // loss/l/(n*mean(f)) == total / sum(f);  f-sum counted BPC times
            out[0] = (float)(lt / ((double)ft / (double)BPC));
        }
    }
}

extern "C" void kernel_launch(void* const* d_in, const int* in_sizes, int n_in,
                              void* d_out, int out_size)
{
    const float* y_true  = (const float*)d_in[0];
    const float* y_pred  = (const float*)d_in[1];
    const float* y_diff  = (const float*)d_in[2];
    const float* weights = (const float*)d_in[3];
    loss_k<<<GRID, THREADS>>>(y_true, y_pred, y_diff, weights, (float*)d_out);
}